// round 14
// baseline (speedup 1.0000x reference)
#include <cuda_runtime.h>

#define IMG 224
#define NPIX (IMG * IMG)        // 50176
#define NUM_VIEWS 6
#define NBATCH 16
#define NPTS 32768
#define THREADS 1024
#define NGROUPS (NPTS / 4)          // 8192 float4-groups of 4 points
#define NITERS (NGROUPS / THREADS)  // 8 iterations, exact

// Padded accumulator: rows -2..225 (pad 2 top/bottom), cols -4..227 (pad 4
// left so the output region starts 16B-aligned). Border rows/cols absorb
// out-of-bounds splats == reference "drop" semantics.
#define AH 228
#define AW 232
#define ASZ (AH * AW)               // 52896 floats = 211584 bytes
#define ROWPAD 2
#define COLPAD 4

__global__ __launch_bounds__(THREADS, 1)
void render_kernel(const float* __restrict__ points, float* __restrict__ out) {
    extern __shared__ float simg[];          // ASZ floats (padded accumulator)
    __shared__ float red_min[32], red_max[32];

    const int bv  = blockIdx.x;
    const int b   = bv / NUM_VIEWS;
    const int v   = bv % NUM_VIEWS;
    const int tid = threadIdx.x;
    const int wid = tid >> 5, lid = tid & 31;

    const float deg2rad = 0.017453292519943295f;
    const float a = (float)(v * 60) * deg2rad;
    const float el_tab[NUM_VIEWS] = {0.f, 30.f, -30.f, 0.f, 0.f, 0.f};
    const float e = el_tab[v] * deg2rad;
    const float ca = cosf(a), sa = sinf(a), ce = cosf(e), se = sinf(e);
    // fused z_fin coefficients (pass 1 only; perturbs zmin/zmax by ulps)
    const float kx = sa * ce, ky = se, kz = ca * ce;

    const float4* __restrict__ pb4 =
        (const float4*)(points + (size_t)b * NPTS * 3);

    // ---- Pass 1: zmin/zmax of z_fin, double-buffered loads; padded-image
    // zeroing folded into the loop to hide cold DRAM latency ----
    float zmn = INFINITY, zmx = -INFINITY;
    {
        float4* s4 = (float4*)simg;
        const float4 zv = make_float4(0.f, 0.f, 0.f, 0.f);
        float4 c0 = pb4[3 * tid + 0];
        float4 c1 = pb4[3 * tid + 1];
        float4 c2 = pb4[3 * tid + 2];
        #pragma unroll 1
        for (int it = 0; it < NITERS; it++) {
            float4 n0, n1, n2;
            if (it < NITERS - 1) {
                int gn = 3 * (tid + (it + 1) * THREADS);
                n0 = pb4[gn + 0];
                n1 = pb4[gn + 1];
                n2 = pb4[gn + 2];
            }
            // zero two image slices (16384 slots cover ASZ/4 = 13224)
            int zi = tid + it * 2048;
            if (zi < ASZ / 4) s4[zi] = zv;
            zi += 1024;
            if (zi < ASZ / 4) s4[zi] = zv;

            float xs[4] = {c0.x, c0.w, c1.z, c2.y};
            float ys[4] = {c0.y, c1.x, c1.w, c2.z};
            float zs[4] = {c0.z, c1.y, c2.x, c2.w};
            #pragma unroll
            for (int k = 0; k < 4; k++) {
                float zf = xs[k] * kx + ys[k] * ky + zs[k] * kz;
                zmn = fminf(zmn, zf);
                zmx = fmaxf(zmx, zf);
            }
            c0 = n0; c1 = n1; c2 = n2;
        }
    }
    #pragma unroll
    for (int o = 16; o > 0; o >>= 1) {
        zmn = fminf(zmn, __shfl_xor_sync(0xffffffffu, zmn, o));
        zmx = fmaxf(zmx, __shfl_xor_sync(0xffffffffu, zmx, o));
    }
    if (lid == 0) { red_min[wid] = zmn; red_max[wid] = zmx; }
    __syncthreads();
    if (wid == 0) {
        zmn = red_min[lid];
        zmx = red_max[lid];
        #pragma unroll
        for (int o = 16; o > 0; o >>= 1) {
            zmn = fminf(zmn, __shfl_xor_sync(0xffffffffu, zmn, o));
            zmx = fmaxf(zmx, __shfl_xor_sync(0xffffffffu, zmx, o));
        }
        if (lid == 0) { red_min[0] = zmn; red_max[0] = zmx; }
    }
    __syncthreads();
    zmn = red_min[0];
    const float scale = 0.7f / (red_max[0] - zmn + 1e-6f);   // hoisted reciprocal
    const float fc = 0.3f - zmn * scale;                     // feat = zf*scale + fc

    // ---- Pass 2: rotate + splat into padded image ----
    const float off0 = -2.0f / 224.0f;
    const float off4 =  2.0f / 224.0f;
    int* iimg = (int*)simg;

    {
        float4 c0 = pb4[3 * tid + 0];
        float4 c1 = pb4[3 * tid + 1];
        float4 c2 = pb4[3 * tid + 2];
        #pragma unroll 1
        for (int it = 0; it < NITERS; it++) {
            float4 n0, n1, n2;
            if (it < NITERS - 1) {
                int gn = 3 * (tid + (it + 1) * THREADS);
                n0 = pb4[gn + 0];
                n1 = pb4[gn + 1];
                n2 = pb4[gn + 2];
            }
            float xs[4] = {c0.x, c0.w, c1.z, c2.y};
            float ys[4] = {c0.y, c1.x, c1.w, c2.z};
            float zs[4] = {c0.z, c1.y, c2.x, c2.w};
            #pragma unroll
            for (int k = 0; k < 4; k++) {
                float x = xs[k], y = ys[k], z = zs[k];
                float xr = x * ca - z * sa;
                float zr = x * sa + z * ca;
                float yr = y * ce - zr * se;
                float zf = y * se + zr * ce;

                // identical fp expressions to the reference path (bit-exact
                // pixel coverage)
                int px0 = (int)((xr + off0 + 1.0f) * 0.5f * (float)(IMG - 1));
                int px4 = (int)((xr + off4 + 1.0f) * 0.5f * (float)(IMG - 1));
                int py0 = (int)((yr + off0 + 1.0f) * 0.5f * (float)(IMG - 1));
                int py4 = (int)((yr + off4 + 1.0f) * 0.5f * (float)(IMG - 1));

                float feat = fmaf(zf, scale, fc);   // in [0.3, 1.0]
                int fb = __float_as_int(feat);      // positive floats order as ints

                bool w2 = ((px4 - px0) == 2) & ((py4 - py0) == 2);
                bool inb = (px0 >= -2) & (px0 <= IMG - 1) &
                           (py0 >= -2) & (py0 <= IMG - 1);

                if (w2 & inb) {
                    // full 3x3 at constant offsets; border absorbs OOB (drop)
                    int base = (py0 + ROWPAD) * AW + (px0 + COLPAD);
                    atomicMax(&iimg[base],          fb);
                    atomicMax(&iimg[base + 1],      fb);
                    atomicMax(&iimg[base + 2],      fb);
                    atomicMax(&iimg[base + AW],     fb);
                    atomicMax(&iimg[base + AW + 1], fb);
                    atomicMax(&iimg[base + AW + 2], fb);
                    atomicMax(&iimg[base + 2*AW],     fb);
                    atomicMax(&iimg[base + 2*AW + 1], fb);
                    atomicMax(&iimg[base + 2*AW + 2], fb);
                } else {
                    // rare: clamped rect into the padded image (exact)
                    int xlo = max(px0, 0), xhi = min(px4, IMG - 1);
                    int ylo = max(py0, 0), yhi = min(py4, IMG - 1);
                    if (xlo <= xhi && ylo <= yhi) {
                        for (int qy = ylo; qy <= yhi; qy++) {
                            int rowbase = (qy + ROWPAD) * AW + COLPAD;
                            for (int qx = xlo; qx <= xhi; qx++)
                                atomicMax(&iimg[rowbase + qx], fb);
                        }
                    }
                }
            }
            c0 = n0; c1 = n1; c2 = n2;
        }
    }
    __syncthreads();

    // ---- Epilogue: copy interior to 3 channels of out[b][v][c][h][w] ----
    float* __restrict__ ob = out + (size_t)bv * 3 * NPIX;
    float4* __restrict__ ob4 = (float4*)ob;
    {
        int yy = tid / 56;          // 224/4 = 56 float4 per output row
        int xq = tid - yy * 56;
        for (int i = tid; i < NPIX / 4; i += THREADS) {
            const float4* src = (const float4*)
                (simg + (yy + ROWPAD) * AW + COLPAD) + xq;
            float4 val = *src;
            ob4[i]                = val;
            ob4[i + NPIX / 4]     = val;
            ob4[i + 2 * NPIX / 4] = val;
            yy += 18; xq += 16;             // advance by 1024 float4 slots
            if (xq >= 56) { xq -= 56; yy += 1; }
        }
    }
}

extern "C" void kernel_launch(void* const* d_in, const int* in_sizes, int n_in,
                              void* d_out, int out_size) {
    const float* points = (const float*)d_in[0];
    float* out = (float*)d_out;

    const size_t smem = (size_t)ASZ * sizeof(float);  // 211584 bytes
    cudaFuncSetAttribute(render_kernel,
                         cudaFuncAttributeMaxDynamicSharedMemorySize, (int)smem);

    render_kernel<<<NBATCH * NUM_VIEWS, THREADS, smem>>>(points, out);
}

// round 15
// speedup vs baseline: 1.1280x; 1.1280x over previous
#include <cuda_runtime.h>

#define IMG 224
#define NPIX (IMG * IMG)        // 50176
#define NUM_VIEWS 6
#define NBATCH 16
#define NPTS 32768
#define THREADS 1024
#define NGROUPS (NPTS / 4)          // 8192 float4-groups of 4 points
#define NITERS (NGROUPS / THREADS)  // 8 iterations, exact
#define NQ4 (NPIX / 4)              // 12544 float4 slots in the image

typedef unsigned long long u64;

// ---- packed f32x2 helpers (per-lane IEEE rn, identical to scalar ops) ----
__device__ __forceinline__ u64 pk2(float lo, float hi) {
    u64 r; asm("mov.b64 %0, {%1, %2};" : "=l"(r) : "f"(lo), "f"(hi)); return r;
}
__device__ __forceinline__ void upk2(float& lo, float& hi, u64 v) {
    asm("mov.b64 {%0, %1}, %2;" : "=f"(lo), "=f"(hi) : "l"(v));
}
__device__ __forceinline__ u64 mul2(u64 a, u64 b) {
    u64 r; asm("mul.rn.f32x2 %0, %1, %2;" : "=l"(r) : "l"(a), "l"(b)); return r;
}
__device__ __forceinline__ u64 add2(u64 a, u64 b) {
    u64 r; asm("add.rn.f32x2 %0, %1, %2;" : "=l"(r) : "l"(a), "l"(b)); return r;
}
__device__ __forceinline__ u64 fma2(u64 a, u64 b, u64 c) {
    u64 r; asm("fma.rn.f32x2 %0, %1, %2, %3;" : "=l"(r) : "l"(a), "l"(b), "l"(c)); return r;
}

__global__ __launch_bounds__(THREADS, 1)
void render_kernel(const float* __restrict__ points, float* __restrict__ out) {
    extern __shared__ float simg[];          // NPIX floats (image accumulator)
    __shared__ float red_min[32], red_max[32];

    const int bv  = blockIdx.x;
    const int b   = bv / NUM_VIEWS;
    const int v   = bv % NUM_VIEWS;
    const int tid = threadIdx.x;
    const int wid = tid >> 5, lid = tid & 31;

    const float deg2rad = 0.017453292519943295f;
    const float a = (float)(v * 60) * deg2rad;
    const float el_tab[NUM_VIEWS] = {0.f, 30.f, -30.f, 0.f, 0.f, 0.f};
    const float e = el_tab[v] * deg2rad;
    const float ca = cosf(a), sa = sinf(a), ce = cosf(e), se = sinf(e);

    // packed broadcast constants
    const u64 ca2  = pk2(ca, ca),   sa2  = pk2(sa, sa);
    const u64 nsa2 = pk2(-sa, -sa), ce2  = pk2(ce, ce);
    const u64 nse2 = pk2(-se, -se), se2  = pk2(se, se);
    const u64 kx2  = pk2(sa * ce, sa * ce);
    const u64 ky2  = pk2(se, se);
    const u64 kz2  = pk2(ca * ce, ca * ce);
    const float off0 = -2.0f / 224.0f;
    const float off4 =  2.0f / 224.0f;
    const u64 o02   = pk2(off0, off0), o42 = pk2(off4, off4);
    const u64 one2  = pk2(1.0f, 1.0f);
    const u64 half2 = pk2(0.5f, 0.5f);
    const u64 cI2   = pk2((float)(IMG - 1), (float)(IMG - 1));

    const float4* __restrict__ pb4 =
        (const float4*)(points + (size_t)b * NPTS * 3);

    // ---- Pass 1: zmin/zmax of z_fin, packed dot products; image zeroing
    // folded into the loop to hide cold DRAM latency ----
    float zmn = INFINITY, zmx = -INFINITY;
    {
        float4* s4 = (float4*)simg;
        const float4 zv = make_float4(0.f, 0.f, 0.f, 0.f);
        float4 c0 = pb4[3 * tid + 0];
        float4 c1 = pb4[3 * tid + 1];
        float4 c2 = pb4[3 * tid + 2];
        #pragma unroll 1
        for (int it = 0; it < NITERS; it++) {
            float4 n0, n1, n2;
            if (it < NITERS - 1) {
                int gn = 3 * (tid + (it + 1) * THREADS);
                n0 = pb4[gn + 0];
                n1 = pb4[gn + 1];
                n2 = pb4[gn + 2];
            }
            int zi = tid + it * 2048;
            if (zi < NQ4) s4[zi] = zv;
            zi += 1024;
            if (zi < NQ4) s4[zi] = zv;

            #pragma unroll
            for (int h = 0; h < 2; h++) {
                u64 X = h ? pk2(c1.z, c2.y) : pk2(c0.x, c0.w);
                u64 Y = h ? pk2(c1.w, c2.z) : pk2(c0.y, c1.x);
                u64 Z = h ? pk2(c2.x, c2.w) : pk2(c0.z, c1.y);
                u64 zf2 = fma2(Z, kz2, fma2(Y, ky2, mul2(X, kx2)));
                float za, zb; upk2(za, zb, zf2);
                zmn = fminf(zmn, fminf(za, zb));
                zmx = fmaxf(zmx, fmaxf(za, zb));
            }
            c0 = n0; c1 = n1; c2 = n2;
        }
    }
    #pragma unroll
    for (int o = 16; o > 0; o >>= 1) {
        zmn = fminf(zmn, __shfl_xor_sync(0xffffffffu, zmn, o));
        zmx = fmaxf(zmx, __shfl_xor_sync(0xffffffffu, zmx, o));
    }
    if (lid == 0) { red_min[wid] = zmn; red_max[wid] = zmx; }
    __syncthreads();
    if (wid == 0) {
        zmn = red_min[lid];
        zmx = red_max[lid];
        #pragma unroll
        for (int o = 16; o > 0; o >>= 1) {
            zmn = fminf(zmn, __shfl_xor_sync(0xffffffffu, zmn, o));
            zmx = fmaxf(zmx, __shfl_xor_sync(0xffffffffu, zmx, o));
        }
        if (lid == 0) { red_min[0] = zmn; red_max[0] = zmx; }
    }
    __syncthreads();
    zmn = red_min[0];
    const float scale = 0.7f / (red_max[0] - zmn + 1e-6f);
    const float fcv = 0.3f - zmn * scale;                 // feat = zf*scale + fc
    const u64 scale2 = pk2(scale, scale);
    const u64 fc2    = pk2(fcv, fcv);

    // ---- Pass 2: packed rotate/convert + branch-free 3x3 splat ----
    int* iimg = (int*)simg;
    {
        float4 c0 = pb4[3 * tid + 0];
        float4 c1 = pb4[3 * tid + 1];
        float4 c2 = pb4[3 * tid + 2];
        #pragma unroll 1
        for (int it = 0; it < NITERS; it++) {
            float4 n0, n1, n2;
            if (it < NITERS - 1) {
                int gn = 3 * (tid + (it + 1) * THREADS);
                n0 = pb4[gn + 0];
                n1 = pb4[gn + 1];
                n2 = pb4[gn + 2];
            }
            #pragma unroll
            for (int h = 0; h < 2; h++) {
                u64 X = h ? pk2(c1.z, c2.y) : pk2(c0.x, c0.w);
                u64 Y = h ? pk2(c1.w, c2.z) : pk2(c0.y, c1.x);
                u64 Z = h ? pk2(c2.x, c2.w) : pk2(c0.z, c1.y);

                // rotation (packed; same FMA shape as scalar FFMA(z,-sa,x*ca))
                u64 xr2 = fma2(Z, nsa2, mul2(X, ca2));
                u64 zr2 = fma2(Z, ca2,  mul2(X, sa2));
                u64 yr2 = fma2(zr2, nse2, mul2(Y, ce2));
                u64 zf2 = fma2(zr2, ce2,  mul2(Y, se2));

                // coordinate conversion: ((u + off) + 1) * 0.5 * 223, exact
                // op-for-op the reference sequence (adds then muls)
                u64 px0f = mul2(mul2(add2(add2(xr2, o02), one2), half2), cI2);
                u64 px4f = mul2(mul2(add2(add2(xr2, o42), one2), half2), cI2);
                u64 py0f = mul2(mul2(add2(add2(yr2, o02), one2), half2), cI2);
                u64 py4f = mul2(mul2(add2(add2(yr2, o42), one2), half2), cI2);
                u64 ft2  = fma2(zf2, scale2, fc2);

                float x0a, x0b, x4a, x4b, y0a, y0b, y4a, y4b, fta, ftb;
                upk2(x0a, x0b, px0f);
                upk2(x4a, x4b, px4f);
                upk2(y0a, y0b, py0f);
                upk2(y4a, y4b, py4f);
                upk2(fta, ftb, ft2);

                #pragma unroll
                for (int k = 0; k < 2; k++) {
                    int px0 = (int)(k ? x0b : x0a);
                    int px4 = (int)(k ? x4b : x4a);
                    int py0 = (int)(k ? y0b : y0a);
                    int py4 = (int)(k ? y4b : y4a);

                    int xlo = max(px0, 0), xhi = min(px4, IMG - 1);
                    int ylo = max(py0, 0), yhi = min(py4, IMG - 1);
                    if (xlo > xhi || ylo > yhi) continue;

                    int fb = __float_as_int(k ? ftb : fta);

                    // rect extent <= 3 per axis; min-clamp collapses the
                    // unrolled 3x3 onto the exact valid rect
                    int x1 = min(xlo + 1, xhi);
                    int y1 = min(ylo + 1, yhi);
                    int rA = ylo * IMG, rB = y1 * IMG, rC = yhi * IMG;
                    atomicMax(&iimg[rA + xlo], fb);
                    atomicMax(&iimg[rA + x1 ], fb);
                    atomicMax(&iimg[rA + xhi], fb);
                    atomicMax(&iimg[rB + xlo], fb);
                    atomicMax(&iimg[rB + x1 ], fb);
                    atomicMax(&iimg[rB + xhi], fb);
                    atomicMax(&iimg[rC + xlo], fb);
                    atomicMax(&iimg[rC + x1 ], fb);
                    atomicMax(&iimg[rC + xhi], fb);
                }
            }
            c0 = n0; c1 = n1; c2 = n2;
        }
    }
    __syncthreads();

    // ---- Epilogue: broadcast image to 3 channels of out[b][v][c][h][w] ----
    float* __restrict__ ob = out + (size_t)bv * 3 * NPIX;
    float4* __restrict__ ob4 = (float4*)ob;
    const float4* __restrict__ s4 = (const float4*)simg;
    for (int i = tid; i < NQ4; i += THREADS) {
        float4 val = s4[i];
        ob4[i]           = val;
        ob4[i + NQ4]     = val;
        ob4[i + 2 * NQ4] = val;
    }
}

extern "C" void kernel_launch(void* const* d_in, const int* in_sizes, int n_in,
                              void* d_out, int out_size) {
    const float* points = (const float*)d_in[0];
    float* out = (float*)d_out;

    const size_t smem = (size_t)NPIX * sizeof(float);  // 200704 bytes
    cudaFuncSetAttribute(render_kernel,
                         cudaFuncAttributeMaxDynamicSharedMemorySize, (int)smem);

    render_kernel<<<NBATCH * NUM_VIEWS, THREADS, smem>>>(points, out);
}